// round 1
// baseline (speedup 1.0000x reference)
#include <cuda_runtime.h>

// Problem constants
#define BB 2
#define TT 2048
#define CC 1024
#define HH 16
#define HD 64
#define MM (BB*TT)   // 4096 rows

// Scratch (allocation-free rule: __device__ globals)
__device__ float g_Q[(size_t)MM*CC];
__device__ float g_K[(size_t)MM*CC];
__device__ float g_V[(size_t)MM*CC];
__device__ float g_Y[(size_t)MM*CC];

// ---------------------------------------------------------------------------
// SGEMM: out[M,N] = A[M,K] @ W[K,N] + bias[N]
// 128x128 tile, BK=16, 256 threads, 8x8 per thread.
// ---------------------------------------------------------------------------
__global__ __launch_bounds__(256) void sgemm_bias_kernel(
    const float* __restrict__ A, const float* __restrict__ W,
    const float* __restrict__ bias, float* __restrict__ out,
    int M, int N, int K)
{
    __shared__ float As[16][128];   // transposed A tile
    __shared__ float Bs[16][128];

    const int tid = threadIdx.x;
    const int rowBase = blockIdx.y * 128;
    const int colBase = blockIdx.x * 128;
    const int tx = tid & 15;        // 0..15 -> col group
    const int ty = tid >> 4;        // 0..15 -> row group

    float acc[8][8];
#pragma unroll
    for (int i = 0; i < 8; i++)
#pragma unroll
        for (int j = 0; j < 8; j++) acc[i][j] = 0.f;

    for (int k0 = 0; k0 < K; k0 += 16) {
        // Load A tile: 128 rows x 16 cols = 512 float4, 2 per thread (transposed store)
#pragma unroll
        for (int i = 0; i < 2; i++) {
            int f  = tid + i * 256;
            int r  = f >> 2;
            int c4 = (f & 3) * 4;
            float4 v = *(const float4*)(A + (size_t)(rowBase + r) * K + k0 + c4);
            As[c4 + 0][r] = v.x;
            As[c4 + 1][r] = v.y;
            As[c4 + 2][r] = v.z;
            As[c4 + 3][r] = v.w;
        }
        // Load B tile: 16 rows x 128 cols = 512 float4, 2 per thread
#pragma unroll
        for (int i = 0; i < 2; i++) {
            int f  = tid + i * 256;
            int r  = f >> 5;
            int c4 = (f & 31) * 4;
            *(float4*)&Bs[r][c4] =
                *(const float4*)(W + (size_t)(k0 + r) * N + colBase + c4);
        }
        __syncthreads();

#pragma unroll
        for (int kk = 0; kk < 16; kk++) {
            float a[8], b[8];
#pragma unroll
            for (int i = 0; i < 8; i += 4) {
                float4 v = *(const float4*)&As[kk][ty * 8 + i];
                a[i] = v.x; a[i+1] = v.y; a[i+2] = v.z; a[i+3] = v.w;
            }
#pragma unroll
            for (int j = 0; j < 8; j += 4) {
                float4 v = *(const float4*)&Bs[kk][tx * 8 + j];
                b[j] = v.x; b[j+1] = v.y; b[j+2] = v.z; b[j+3] = v.w;
            }
#pragma unroll
            for (int i = 0; i < 8; i++)
#pragma unroll
                for (int j = 0; j < 8; j++)
                    acc[i][j] += a[i] * b[j];
        }
        __syncthreads();
    }

    // Epilogue: + bias, float4 stores
#pragma unroll
    for (int i = 0; i < 8; i++) {
        int row = rowBase + ty * 8 + i;
#pragma unroll
        for (int j = 0; j < 8; j += 4) {
            int col = colBase + tx * 8 + j;
            float4 bv = *(const float4*)(bias + col);
            float4 o;
            o.x = acc[i][j + 0] + bv.x;
            o.y = acc[i][j + 1] + bv.y;
            o.z = acc[i][j + 2] + bv.z;
            o.w = acc[i][j + 3] + bv.w;
            *(float4*)(out + (size_t)row * N + col) = o;
        }
    }
}

// ---------------------------------------------------------------------------
// Causal flash attention, fp32.
// grid: (T/128, H, B), 128 threads/block; each thread owns one query row.
// K/V tiles of 16 keys in shared memory, online softmax.
// ---------------------------------------------------------------------------
#define BKV 16

__global__ __launch_bounds__(128) void attn_kernel(
    const float* __restrict__ Q, const float* __restrict__ K,
    const float* __restrict__ V, float* __restrict__ Y)
{
    __shared__ float Ks[BKV][HD];
    __shared__ float Vs[BKV][HD];

    const int tid = threadIdx.x;
    const int qi  = blockIdx.x * 128 + tid;   // query row within sequence
    const int h   = blockIdx.y;
    const int b   = blockIdx.z;

    // load q row, fold in softmax scale 1/sqrt(64)
    const float* Qr = Q + ((size_t)(b * TT + qi)) * CC + h * HD;
    float q[HD];
#pragma unroll
    for (int d = 0; d < HD; d += 4) {
        float4 v = *(const float4*)(Qr + d);
        q[d]   = v.x * 0.125f;
        q[d+1] = v.y * 0.125f;
        q[d+2] = v.z * 0.125f;
        q[d+3] = v.w * 0.125f;
    }

    float accv[HD];
#pragma unroll
    for (int d = 0; d < HD; d++) accv[d] = 0.f;
    float m = -1e30f, l = 0.f;

    const int kend = blockIdx.x * 128 + 127;   // last key any thread in block needs

    for (int k0 = 0; k0 <= kend; k0 += BKV) {
        // cooperative load of K/V tile: 16 rows x 16 float4 each
#pragma unroll
        for (int i = 0; i < 2; i++) {
            int f  = tid + i * 128;
            int r  = f >> 4;
            int c4 = (f & 15) * 4;
            size_t g = ((size_t)(b * TT + k0 + r)) * CC + h * HD + c4;
            *(float4*)&Ks[r][c4] = *(const float4*)(K + g);
            *(float4*)&Vs[r][c4] = *(const float4*)(V + g);
        }
        __syncthreads();

        if (k0 <= qi) {
            float s[BKV];
#pragma unroll
            for (int j = 0; j < BKV; j++) {
                float sj = 0.f;
#pragma unroll
                for (int d = 0; d < HD; d += 4) {
                    float4 kv = *(const float4*)&Ks[j][d];
                    sj += q[d] * kv.x + q[d+1] * kv.y + q[d+2] * kv.z + q[d+3] * kv.w;
                }
                s[j] = (k0 + j > qi) ? -1e30f : sj;
            }
            float mt = m;
#pragma unroll
            for (int j = 0; j < BKV; j++) mt = fmaxf(mt, s[j]);
            float corr = __expf(m - mt);
            float lsum = 0.f;
#pragma unroll
            for (int j = 0; j < BKV; j++) {
                float p = __expf(s[j] - mt);
                s[j] = p;
                lsum += p;
            }
            l = l * corr + lsum;
            m = mt;
#pragma unroll
            for (int d = 0; d < HD; d++) accv[d] *= corr;
#pragma unroll
            for (int j = 0; j < BKV; j++) {
                float p = s[j];
#pragma unroll
                for (int d = 0; d < HD; d += 4) {
                    float4 vv = *(const float4*)&Vs[j][d];
                    accv[d]   += p * vv.x;
                    accv[d+1] += p * vv.y;
                    accv[d+2] += p * vv.z;
                    accv[d+3] += p * vv.w;
                }
            }
        }
        __syncthreads();
    }

    const float inv = 1.f / l;
    float* Yr = g_Y + ((size_t)(b * TT + qi)) * CC + h * HD;
#pragma unroll
    for (int d = 0; d < HD; d += 4) {
        float4 o;
        o.x = accv[d]   * inv;
        o.y = accv[d+1] * inv;
        o.z = accv[d+2] * inv;
        o.w = accv[d+3] * inv;
        *(float4*)(Yr + d) = o;
    }
    (void)Y;
}

// ---------------------------------------------------------------------------
extern "C" void kernel_launch(void* const* d_in, const int* in_sizes, int n_in,
                              void* d_out, int out_size)
{
    const float* x  = (const float*)d_in[0];
    const float* Wq = (const float*)d_in[1];
    const float* bq = (const float*)d_in[2];
    const float* Wk = (const float*)d_in[3];
    const float* bk = (const float*)d_in[4];
    const float* Wv = (const float*)d_in[5];
    const float* bv = (const float*)d_in[6];
    const float* Wp = (const float*)d_in[7];
    const float* bp = (const float*)d_in[8];
    float* out = (float*)d_out;

    float *Q, *Kp, *Vp, *Yp;
    cudaGetSymbolAddress((void**)&Q,  g_Q);
    cudaGetSymbolAddress((void**)&Kp, g_K);
    cudaGetSymbolAddress((void**)&Vp, g_V);
    cudaGetSymbolAddress((void**)&Yp, g_Y);

    dim3 gblk(256);
    dim3 ggrd(CC / 128, MM / 128);

    sgemm_bias_kernel<<<ggrd, gblk>>>(x, Wq, bq, Q,  MM, CC, CC);
    sgemm_bias_kernel<<<ggrd, gblk>>>(x, Wk, bk, Kp, MM, CC, CC);
    sgemm_bias_kernel<<<ggrd, gblk>>>(x, Wv, bv, Vp, MM, CC, CC);

    dim3 agrd(TT / 128, HH, BB);
    attn_kernel<<<agrd, 128>>>(Q, Kp, Vp, Yp);

    sgemm_bias_kernel<<<ggrd, gblk>>>(Yp, Wp, bp, out, MM, CC, CC);

    (void)in_sizes; (void)n_in; (void)out_size;
}

// round 2
// speedup vs baseline: 1.1712x; 1.1712x over previous
#include <cuda_runtime.h>

// Problem constants
#define BB 2
#define TT 2048
#define CC 1024
#define HH 16
#define HD 64
#define MM (BB*TT)   // 4096 rows

// Scratch (allocation-free rule: __device__ globals)
__device__ float g_Q[(size_t)MM*CC];
__device__ float g_K[(size_t)MM*CC];
__device__ float g_V[(size_t)MM*CC];
__device__ float g_Y[(size_t)MM*CC];

// ---------------------------------------------------------------------------
// Packed fp32x2 helpers (SASS FFMA2 path — ptxas never auto-emits this)
// ---------------------------------------------------------------------------
typedef unsigned long long u64;

__device__ __forceinline__ u64 ffma2(u64 a, u64 b, u64 c) {
    u64 d;
    asm("fma.rn.f32x2 %0, %1, %2, %3;" : "=l"(d) : "l"(a), "l"(b), "l"(c));
    return d;
}
__device__ __forceinline__ u64 fadd2(u64 a, u64 b) {
    u64 d;
    asm("add.rn.f32x2 %0, %1, %2;" : "=l"(d) : "l"(a), "l"(b));
    return d;
}
__device__ __forceinline__ u64 fmul2(u64 a, u64 b) {
    u64 d;
    asm("mul.rn.f32x2 %0, %1, %2;" : "=l"(d) : "l"(a), "l"(b));
    return d;
}
__device__ __forceinline__ u64 pack2(float lo, float hi) {
    u64 d;
    asm("mov.b64 %0, {%1, %2};" : "=l"(d) : "f"(lo), "f"(hi));
    return d;
}
__device__ __forceinline__ void unpack2(u64 v, float& lo, float& hi) {
    asm("mov.b64 {%0, %1}, %2;" : "=f"(lo), "=f"(hi) : "l"(v));
}

// ---------------------------------------------------------------------------
// SGEMM: out[M,N] = A[M,K] @ W[K,N] + bias[N]
// 128x128 tile, BK=16, 256 threads, 8x8 per thread in 4x4 quadrants,
// inner product via packed FFMA2.
// ---------------------------------------------------------------------------
__global__ __launch_bounds__(256) void sgemm_bias_kernel(
    const float* __restrict__ A, const float* __restrict__ W,
    const float* __restrict__ bias, float* __restrict__ out,
    int M, int N, int K)
{
    __shared__ float As[16][128];   // transposed A tile: As[k][row]
    __shared__ float Bs[16][128];   // Bs[k][col]

    const int tid = threadIdx.x;
    const int rowBase = blockIdx.y * 128;
    const int colBase = blockIdx.x * 128;
    const int tx = tid & 15;        // col group (4+4 cols, split by 64)
    const int ty = tid >> 4;        // row group (4+4 rows, split by 64)

    u64 acc2[8][4];                 // [row 0..7][col-pair 0..3], quadrant layout
#pragma unroll
    for (int i = 0; i < 8; i++)
#pragma unroll
        for (int j = 0; j < 4; j++) acc2[i][j] = 0ULL;

    for (int k0 = 0; k0 < K; k0 += 16) {
        // Load A tile (transposed store)
#pragma unroll
        for (int i = 0; i < 2; i++) {
            int f  = tid + i * 256;
            int r  = f >> 2;
            int c4 = (f & 3) * 4;
            float4 v = *(const float4*)(A + (size_t)(rowBase + r) * K + k0 + c4);
            As[c4 + 0][r] = v.x;
            As[c4 + 1][r] = v.y;
            As[c4 + 2][r] = v.z;
            As[c4 + 3][r] = v.w;
        }
        // Load B tile
#pragma unroll
        for (int i = 0; i < 2; i++) {
            int f  = tid + i * 256;
            int r  = f >> 5;
            int c4 = (f & 31) * 4;
            *(float4*)&Bs[r][c4] =
                *(const float4*)(W + (size_t)(k0 + r) * N + colBase + c4);
        }
        __syncthreads();

#pragma unroll
        for (int kk = 0; kk < 16; kk++) {
            float4 a0 = *(const float4*)&As[kk][ty * 4];
            float4 a1 = *(const float4*)&As[kk][64 + ty * 4];
            ulonglong2 b0 = *(const ulonglong2*)&Bs[kk][tx * 4];
            ulonglong2 b1 = *(const ulonglong2*)&Bs[kk][64 + tx * 4];

            u64 ad[8];
            ad[0] = pack2(a0.x, a0.x); ad[1] = pack2(a0.y, a0.y);
            ad[2] = pack2(a0.z, a0.z); ad[3] = pack2(a0.w, a0.w);
            ad[4] = pack2(a1.x, a1.x); ad[5] = pack2(a1.y, a1.y);
            ad[6] = pack2(a1.z, a1.z); ad[7] = pack2(a1.w, a1.w);

            u64 bb[4] = { b0.x, b0.y, b1.x, b1.y };

#pragma unroll
            for (int i = 0; i < 8; i++)
#pragma unroll
                for (int j = 0; j < 4; j++)
                    acc2[i][j] = ffma2(ad[i], bb[j], acc2[i][j]);
        }
        __syncthreads();
    }

    // Epilogue: unpack, + bias, float4 stores. Row quadrants: i<4 -> ty*4+i,
    // i>=4 -> 64+ty*4+(i-4). Col quadrants: pairs 0,1 -> tx*4; pairs 2,3 -> 64+tx*4.
#pragma unroll
    for (int i = 0; i < 8; i++) {
        int row = rowBase + ((i < 4) ? (ty * 4 + i) : (64 + ty * 4 + (i - 4)));
#pragma unroll
        for (int q = 0; q < 2; q++) {
            int col = colBase + ((q == 0) ? (tx * 4) : (64 + tx * 4));
            float4 bv = *(const float4*)(bias + col);
            float4 o;
            unpack2(acc2[i][q * 2 + 0], o.x, o.y);
            unpack2(acc2[i][q * 2 + 1], o.z, o.w);
            o.x += bv.x; o.y += bv.y; o.z += bv.z; o.w += bv.w;
            *(float4*)(out + (size_t)row * N + col) = o;
        }
    }
}

// ---------------------------------------------------------------------------
// Causal flash attention, fp32 with packed FFMA2 inner loops.
// grid: (T/128, H, B), 128 threads/block; each thread owns one query row.
// Heavy (late) query blocks are scheduled first (reverse mapping).
// ---------------------------------------------------------------------------
#define BKV 16

__global__ __launch_bounds__(128) void attn_kernel(
    const float* __restrict__ Q, const float* __restrict__ K,
    const float* __restrict__ V, float* __restrict__ Y)
{
    __shared__ float Ks[BKV][HD];
    __shared__ float Vs[BKV][HD];

    const int tid = threadIdx.x;
    const int qb  = gridDim.x - 1 - blockIdx.x;  // heavy blocks launch first
    const int qi  = qb * 128 + tid;              // query row within sequence
    const int h   = blockIdx.y;
    const int b   = blockIdx.z;

    // load q row, fold in softmax scale 1/sqrt(64), pack into fp32x2 pairs
    const float* Qr = Q + ((size_t)(b * TT + qi)) * CC + h * HD;
    u64 q2[HD / 2];
#pragma unroll
    for (int d = 0; d < HD; d += 4) {
        float4 v = *(const float4*)(Qr + d);
        q2[d / 2]     = pack2(v.x * 0.125f, v.y * 0.125f);
        q2[d / 2 + 1] = pack2(v.z * 0.125f, v.w * 0.125f);
    }

    u64 accv2[HD / 2];
#pragma unroll
    for (int t = 0; t < HD / 2; t++) accv2[t] = 0ULL;
    float m = -1e30f, l = 0.f;

    const int kend = qb * 128 + 127;   // last key any thread in block needs

    for (int k0 = 0; k0 <= kend; k0 += BKV) {
        // cooperative load of K/V tile: 16 rows x 16 float4 each
#pragma unroll
        for (int i = 0; i < 2; i++) {
            int f  = tid + i * 128;
            int r  = f >> 4;
            int c4 = (f & 15) * 4;
            size_t g = ((size_t)(b * TT + k0 + r)) * CC + h * HD + c4;
            *(float4*)&Ks[r][c4] = *(const float4*)(K + g);
            *(float4*)&Vs[r][c4] = *(const float4*)(V + g);
        }
        __syncthreads();

        if (k0 <= qi) {
            float s[BKV];
#pragma unroll
            for (int j = 0; j < BKV; j++) {
                const ulonglong2* krow = (const ulonglong2*)&Ks[j][0];
                u64 pA = 0, pB = 0, pC = 0, pD = 0;   // 4 rotating packed partials
#pragma unroll
                for (int t = 0; t < 16; t += 2) {
                    ulonglong2 kv0 = krow[t];
                    ulonglong2 kv1 = krow[t + 1];
                    pA = ffma2(q2[2 * t + 0], kv0.x, pA);
                    pB = ffma2(q2[2 * t + 1], kv0.y, pB);
                    pC = ffma2(q2[2 * t + 2], kv1.x, pC);
                    pD = ffma2(q2[2 * t + 3], kv1.y, pD);
                }
                u64 r2 = fadd2(fadd2(pA, pB), fadd2(pC, pD));
                float lo, hi;
                unpack2(r2, lo, hi);
                float sj = lo + hi;
                s[j] = (k0 + j > qi) ? -1e30f : sj;
            }
            float mt = m;
#pragma unroll
            for (int j = 0; j < BKV; j++) mt = fmaxf(mt, s[j]);
            float corr = __expf(m - mt);
            float lsum = 0.f;
#pragma unroll
            for (int j = 0; j < BKV; j++) {
                float p = __expf(s[j] - mt);
                s[j] = p;
                lsum += p;
            }
            l = l * corr + lsum;
            m = mt;
            u64 corr2 = pack2(corr, corr);
#pragma unroll
            for (int t = 0; t < HD / 2; t++) accv2[t] = fmul2(accv2[t], corr2);
#pragma unroll
            for (int j = 0; j < BKV; j++) {
                u64 pd = pack2(s[j], s[j]);
                const ulonglong2* vrow = (const ulonglong2*)&Vs[j][0];
#pragma unroll
                for (int t = 0; t < 16; t++) {
                    ulonglong2 vv = vrow[t];
                    accv2[2 * t + 0] = ffma2(pd, vv.x, accv2[2 * t + 0]);
                    accv2[2 * t + 1] = ffma2(pd, vv.y, accv2[2 * t + 1]);
                }
            }
        }
        __syncthreads();
    }

    const float inv = 1.f / l;
    float* Yr = g_Y + ((size_t)(b * TT + qi)) * CC + h * HD;
#pragma unroll
    for (int t = 0; t < 16; t++) {
        float4 o;
        unpack2(accv2[2 * t + 0], o.x, o.y);
        unpack2(accv2[2 * t + 1], o.z, o.w);
        o.x *= inv; o.y *= inv; o.z *= inv; o.w *= inv;
        *(float4*)(Yr + t * 4) = o;
    }
    (void)Y;
}

// ---------------------------------------------------------------------------
extern "C" void kernel_launch(void* const* d_in, const int* in_sizes, int n_in,
                              void* d_out, int out_size)
{
    const float* x  = (const float*)d_in[0];
    const float* Wq = (const float*)d_in[1];
    const float* bq = (const float*)d_in[2];
    const float* Wk = (const float*)d_in[3];
    const float* bk = (const float*)d_in[4];
    const float* Wv = (const float*)d_in[5];
    const float* bv = (const float*)d_in[6];
    const float* Wp = (const float*)d_in[7];
    const float* bp = (const float*)d_in[8];
    float* out = (float*)d_out;

    float *Q, *Kp, *Vp, *Yp;
    cudaGetSymbolAddress((void**)&Q,  g_Q);
    cudaGetSymbolAddress((void**)&Kp, g_K);
    cudaGetSymbolAddress((void**)&Vp, g_V);
    cudaGetSymbolAddress((void**)&Yp, g_Y);

    dim3 gblk(256);
    dim3 ggrd(CC / 128, MM / 128);

    sgemm_bias_kernel<<<ggrd, gblk>>>(x, Wq, bq, Q,  MM, CC, CC);
    sgemm_bias_kernel<<<ggrd, gblk>>>(x, Wk, bk, Kp, MM, CC, CC);
    sgemm_bias_kernel<<<ggrd, gblk>>>(x, Wv, bv, Vp, MM, CC, CC);

    dim3 agrd(TT / 128, HH, BB);
    attn_kernel<<<agrd, 128>>>(Q, Kp, Vp, Yp);

    sgemm_bias_kernel<<<ggrd, gblk>>>(Yp, Wp, bp, out, MM, CC, CC);

    (void)in_sizes; (void)n_in; (void)out_size;
}

// round 7
// speedup vs baseline: 1.6038x; 1.3695x over previous
#include <cuda_runtime.h>
#include <cuda_bf16.h>
#include <cstdint>

// Problem constants
#define BB 2
#define TT 2048
#define CC 1024
#define HH 16
#define HD 64
#define MM (BB*TT)   // 4096 rows

// ---------------------------------------------------------------------------
// Scratch (__device__ globals: allocation-free rule)
// ---------------------------------------------------------------------------
__device__ float g_Q[(size_t)MM*CC];
__device__ float g_K[(size_t)MM*CC];
__device__ float g_V[(size_t)MM*CC];
__device__ __nv_bfloat16 g_Xh[(size_t)MM*CC];
__device__ __nv_bfloat16 g_Xl[(size_t)MM*CC];
__device__ __nv_bfloat16 g_Yh[(size_t)MM*CC];
__device__ __nv_bfloat16 g_Yl[(size_t)MM*CC];
__device__ __nv_bfloat16 g_Wth[(size_t)4*CC*CC];  // 4 transposed weights, hi
__device__ __nv_bfloat16 g_Wtl[(size_t)4*CC*CC];  // lo

typedef unsigned long long u64;

__device__ __forceinline__ uint32_t smem_u32(const void* p) {
    uint32_t a;
    asm("{ .reg .u64 t; cvta.to.shared.u64 t, %1; cvt.u32.u64 %0, t; }" : "=r"(a) : "l"(p));
    return a;
}
__device__ __forceinline__ void cp_async16(uint32_t saddr, const void* gaddr) {
    asm volatile("cp.async.ca.shared.global [%0], [%1], 16;" :: "r"(saddr), "l"(gaddr));
}
#define CP_COMMIT() asm volatile("cp.async.commit_group;" ::: "memory")

__device__ __forceinline__ void ldmat_x4(uint32_t* r, uint32_t addr) {
    asm volatile("ldmatrix.sync.aligned.m8n8.x4.shared.b16 {%0,%1,%2,%3}, [%4];"
        : "=r"(r[0]), "=r"(r[1]), "=r"(r[2]), "=r"(r[3]) : "r"(addr));
}
__device__ __forceinline__ void ldmat_x2(uint32_t* r, uint32_t addr) {
    asm volatile("ldmatrix.sync.aligned.m8n8.x2.shared.b16 {%0,%1}, [%2];"
        : "=r"(r[0]), "=r"(r[1]) : "r"(addr));
}
__device__ __forceinline__ void mma_bf16(float* c, const uint32_t* a, const uint32_t* b) {
    asm volatile("mma.sync.aligned.m16n8k16.row.col.f32.bf16.bf16.f32 "
        "{%0,%1,%2,%3}, {%4,%5,%6,%7}, {%8,%9}, {%0,%1,%2,%3};"
        : "+f"(c[0]), "+f"(c[1]), "+f"(c[2]), "+f"(c[3])
        : "r"(a[0]), "r"(a[1]), "r"(a[2]), "r"(a[3]), "r"(b[0]), "r"(b[1]));
}

// ---------------------------------------------------------------------------
// Split-precision conversion kernels
// ---------------------------------------------------------------------------
__device__ __forceinline__ void split_bf16(float v, __nv_bfloat16& h, __nv_bfloat16& l) {
    h = __float2bfloat16(v);
    l = __float2bfloat16(v - __bfloat162float(h));
}

__global__ void convert_split_kernel(const float* __restrict__ in,
                                     __nv_bfloat16* __restrict__ oh,
                                     __nv_bfloat16* __restrict__ ol, int n4)
{
    for (int i = blockIdx.x * blockDim.x + threadIdx.x; i < n4; i += gridDim.x * blockDim.x) {
        float4 v = ((const float4*)in)[i];
        __nv_bfloat16 h0,l0,h1,l1,h2,l2,h3,l3;
        split_bf16(v.x,h0,l0); split_bf16(v.y,h1,l1);
        split_bf16(v.z,h2,l2); split_bf16(v.w,h3,l3);
        ((__nv_bfloat162*)oh)[2*i]   = __halves2bfloat162(h0,h1);
        ((__nv_bfloat162*)oh)[2*i+1] = __halves2bfloat162(h2,h3);
        ((__nv_bfloat162*)ol)[2*i]   = __halves2bfloat162(l0,l1);
        ((__nv_bfloat162*)ol)[2*i+1] = __halves2bfloat162(l2,l3);
    }
}

// W[K=1024,N=1024] -> Wt[N,K] split into hi/lo bf16
__global__ void transpose_split_kernel(const float* __restrict__ W,
                                       __nv_bfloat16* __restrict__ Th,
                                       __nv_bfloat16* __restrict__ Tl)
{
    __shared__ float t[32][33];
    int xi = blockIdx.x * 32 + threadIdx.x;   // n
    int yi = blockIdx.y * 32 + threadIdx.y;   // k
#pragma unroll
    for (int j = 0; j < 32; j += 8)
        t[threadIdx.y + j][threadIdx.x] = W[(size_t)(yi + j) * CC + xi];
    __syncthreads();
    int xo = blockIdx.y * 32 + threadIdx.x;   // k
    int yo = blockIdx.x * 32 + threadIdx.y;   // n
#pragma unroll
    for (int j = 0; j < 32; j += 8) {
        float v = t[threadIdx.x][threadIdx.y + j];
        __nv_bfloat16 h, l;
        split_bf16(v, h, l);
        Th[(size_t)(yo + j) * CC + xo] = h;
        Tl[(size_t)(yo + j) * CC + xo] = l;
    }
}

// ---------------------------------------------------------------------------
// mma.sync split-bf16 GEMM: out[4096,1024] = A @ Wt^T + bias
// A as (Ah,Al) bf16 [M,K] row-major; Wt as (Bh,Bl) bf16 [N,K] (k-contiguous).
// CTA tile 128x128, BK=32, 256 threads (8 warps, 2x4; warp tile 64x32).
// D = Ah*Bh + Ah*Bl + Al*Bh.  cp.async double buffered.
// ---------------------------------------------------------------------------
#define BK 32
#define PITCH 40                       // bf16 elements per smem row (80 B)
#define TILE_BYTES (128 * PITCH * 2)   // 10240 B per array per stage
#define AH_OFF 0
#define AL_OFF (2 * TILE_BYTES)
#define BH_OFF (4 * TILE_BYTES)
#define BL_OFF (6 * TILE_BYTES)
#define GEMM_SMEM (8 * TILE_BYTES)     // 81920 B

__global__ __launch_bounds__(256) void gemm_mma_kernel(
    const __nv_bfloat16* __restrict__ Ah, const __nv_bfloat16* __restrict__ Al,
    const __nv_bfloat16* __restrict__ Bh, const __nv_bfloat16* __restrict__ Bl,
    const float* __restrict__ bias, float* __restrict__ out)
{
    extern __shared__ char smem[];
    const uint32_t sbase = smem_u32(smem);
    const int tid  = threadIdx.x;
    const int lane = tid & 31;
    const int wid  = tid >> 5;
    const int warp_m = wid >> 2;       // 0..1  (64 rows each)
    const int warp_n = wid & 3;        // 0..3  (32 cols each)

    const int rowBase = blockIdx.y * 128;
    const int colBase = blockIdx.x * 128;

    float acc[4][4][4];
#pragma unroll
    for (int i = 0; i < 4; i++)
#pragma unroll
        for (int j = 0; j < 4; j++)
#pragma unroll
            for (int r = 0; r < 4; r++) acc[i][j][r] = 0.f;

    // stage loader: 512 16B-vectors per array; 2 iters x 256 threads
    auto load_stage = [&](int stg, int kc0) {
        const uint32_t so = (uint32_t)stg * TILE_BYTES;
#pragma unroll
        for (int it = 0; it < 2; it++) {
            int v = tid + it * 256;
            int r = v >> 2;
            int cv = v & 3;
            uint32_t doff = so + (uint32_t)(r * 80 + cv * 16);
            size_t gA = (size_t)(rowBase + r) * CC + kc0 + cv * 8;
            size_t gB = (size_t)(colBase + r) * CC + kc0 + cv * 8;
            cp_async16(sbase + AH_OFF + doff, Ah + gA);
            cp_async16(sbase + AL_OFF + doff, Al + gA);
            cp_async16(sbase + BH_OFF + doff, Bh + gB);
            cp_async16(sbase + BL_OFF + doff, Bl + gB);
        }
        CP_COMMIT();
    };

    // ldmatrix lane addressing (precomputed pieces)
    const int arow  = (lane & 7) + ((lane >> 3) & 1) * 8;   // row within m16
    const int akoff = (lane >> 4) * 8;                      // +0 / +8 k cols
    const int l2    = lane & 15;
    const int brow  = l2 & 7;                               // row within n8
    const int bkoff = (l2 >> 3) * 8;

    auto compute_stage = [&](int stg) {
        const uint32_t so = (uint32_t)stg * TILE_BYTES;
#pragma unroll
        for (int ks = 0; ks < 2; ks++) {
            const int k0 = ks * 16;
            uint32_t ah[4][4], al[4][4], bh[4][2], bl[4][2];
#pragma unroll
            for (int mt = 0; mt < 4; mt++) {
                int row = warp_m * 64 + mt * 16 + arow;
                uint32_t off = so + (uint32_t)(row * 80 + (k0 + akoff) * 2);
                ldmat_x4(ah[mt], sbase + AH_OFF + off);
                ldmat_x4(al[mt], sbase + AL_OFF + off);
            }
#pragma unroll
            for (int nt = 0; nt < 4; nt++) {
                int row = warp_n * 32 + nt * 8 + brow;
                uint32_t off = so + (uint32_t)(row * 80 + (k0 + bkoff) * 2);
                ldmat_x2(bh[nt], sbase + BH_OFF + off);
                ldmat_x2(bl[nt], sbase + BL_OFF + off);
            }
#pragma unroll
            for (int mt = 0; mt < 4; mt++)
#pragma unroll
                for (int nt = 0; nt < 4; nt++) {
                    mma_bf16(acc[mt][nt], ah[mt], bh[nt]);
                    mma_bf16(acc[mt][nt], ah[mt], bl[nt]);
                    mma_bf16(acc[mt][nt], al[mt], bh[nt]);
                }
        }
    };

    const int NCHUNK = CC / BK;   // 32
    load_stage(0, 0);
    for (int c = 0; c < NCHUNK; c++) {
        if (c + 1 < NCHUNK) {
            load_stage((c + 1) & 1, (c + 1) * BK);
            asm volatile("cp.async.wait_group 1;" ::: "memory");
        } else {
            asm volatile("cp.async.wait_group 0;" ::: "memory");
        }
        __syncthreads();
        compute_stage(c & 1);
        __syncthreads();
    }

    // Epilogue: + bias, float2 stores
    const int g   = lane >> 2;
    const int tg2 = (lane & 3) * 2;
#pragma unroll
    for (int mt = 0; mt < 4; mt++) {
        int row0 = rowBase + warp_m * 64 + mt * 16 + g;
#pragma unroll
        for (int nt = 0; nt < 4; nt++) {
            int col = colBase + warp_n * 32 + nt * 8 + tg2;
            float2 bv = *(const float2*)(bias + col);
            float2 o0, o1;
            o0.x = acc[mt][nt][0] + bv.x;
            o0.y = acc[mt][nt][1] + bv.y;
            o1.x = acc[mt][nt][2] + bv.x;
            o1.y = acc[mt][nt][3] + bv.y;
            *(float2*)(out + (size_t)row0 * CC + col) = o0;
            *(float2*)(out + (size_t)(row0 + 8) * CC + col) = o1;
        }
    }
}

// ---------------------------------------------------------------------------
// Packed fp32x2 helpers for attention
// ---------------------------------------------------------------------------
__device__ __forceinline__ u64 ffma2(u64 a, u64 b, u64 c) {
    u64 d; asm("fma.rn.f32x2 %0, %1, %2, %3;" : "=l"(d) : "l"(a), "l"(b), "l"(c)); return d;
}
__device__ __forceinline__ u64 fadd2(u64 a, u64 b) {
    u64 d; asm("add.rn.f32x2 %0, %1, %2;" : "=l"(d) : "l"(a), "l"(b)); return d;
}
__device__ __forceinline__ u64 fmul2(u64 a, u64 b) {
    u64 d; asm("mul.rn.f32x2 %0, %1, %2;" : "=l"(d) : "l"(a), "l"(b)); return d;
}
__device__ __forceinline__ u64 pack2(float lo, float hi) {
    u64 d; asm("mov.b64 %0, {%1, %2};" : "=l"(d) : "f"(lo), "f"(hi)); return d;
}
__device__ __forceinline__ void unpack2(u64 v, float& lo, float& hi) {
    asm("mov.b64 {%0, %1}, %2;" : "=f"(lo), "=f"(hi) : "l"(v));
}

// ---------------------------------------------------------------------------
// Causal flash attention, fp32 FFMA2; outputs bf16 hi/lo for the proj GEMM.
// ---------------------------------------------------------------------------
#define BKV 16

__global__ __launch_bounds__(128) void attn_kernel(
    const float* __restrict__ Q, const float* __restrict__ K,
    const float* __restrict__ V)
{
    __shared__ float Ks[BKV][HD];
    __shared__ float Vs[BKV][HD];

    const int tid = threadIdx.x;
    const int qb  = gridDim.x - 1 - blockIdx.x;  // heavy blocks first
    const int qi  = qb * 128 + tid;
    const int h   = blockIdx.y;
    const int b   = blockIdx.z;

    const float* Qr = Q + ((size_t)(b * TT + qi)) * CC + h * HD;
    u64 q2[HD / 2];
#pragma unroll
    for (int d = 0; d < HD; d += 4) {
        float4 v = *(const float4*)(Qr + d);
        q2[d / 2]     = pack2(v.x * 0.125f, v.y * 0.125f);
        q2[d / 2 + 1] = pack2(v.z * 0.125f, v.w * 0.125f);
    }

    u64 accv2[HD / 2];
#pragma unroll
    for (int t = 0; t < HD / 2; t++) accv2[t] = 0ULL;
    float m = -1e30f, l = 0.f;

    const int kend = qb * 128 + 127;

    for (int k0 = 0; k0 <= kend; k0 += BKV) {
#pragma unroll
        for (int i = 0; i < 2; i++) {
            int f  = tid + i * 128;
            int r  = f >> 4;
            int c4 = (f & 15) * 4;
            size_t g = ((size_t)(b * TT + k0 + r)) * CC + h * HD + c4;
            *(float4*)&Ks[r][c4] = *(const float4*)(K + g);
            *(float4*)&Vs[r][c4] = *(const float4*)(V + g);
        }
        __syncthreads();

        if (k0 <= qi) {
            float s[BKV];
#pragma unroll
            for (int j = 0; j < BKV; j++) {
                const ulonglong2* krow = (const ulonglong2*)&Ks[j][0];
                u64 pA = 0, pB = 0, pC = 0, pD = 0;
#pragma unroll
                for (int t = 0; t < 16; t += 2) {
                    ulonglong2 kv0 = krow[t];
                    ulonglong2 kv1 = krow[t + 1];
                    pA = ffma2(q2[2 * t + 0], kv0.x, pA);
                    pB = ffma2(q2[2 * t + 1], kv0.y, pB);
                    pC = ffma2(q2[2 * t + 2], kv1.x, pC);
                    pD = ffma2(q2[2 * t + 3], kv1.y, pD);
                }
                u64 r2 = fadd2(fadd2(pA, pB), fadd2(pC, pD));
                float lo, hi;
                unpack2(r2, lo, hi);
                float sj = lo + hi;
                s[j] = (k0 + j > qi) ? -1e30f : sj;
            }
            float mt = m;
#pragma unroll
            for (int j = 0; j < BKV; j++) mt = fmaxf(mt, s[j]);
            float corr = __expf(m - mt);
            float lsum = 0.f;
#pragma unroll
            for (int j = 0; j < BKV; j++) {
                float p = __expf(s[j] - mt);
                s[j] = p;
                lsum += p;
            }
            l = l * corr + lsum;
            m = mt;
            u64 corr2 = pack2(corr, corr);
#pragma unroll
            for (int t = 0; t < HD / 2; t++) accv2[t] = fmul2(accv2[t], corr2);
#pragma unroll
            for (int j = 0; j < BKV; j++) {
                u64 pd = pack2(s[j], s[j]);
                const ulonglong2* vrow = (const ulonglong2*)&Vs[j][0];
#pragma unroll
                for (int t = 0; t < 16; t++) {
                    ulonglong2 vv = vrow[t];
                    accv2[2 * t + 0] = ffma2(pd, vv.x, accv2[2 * t + 0]);
                    accv2[2 * t + 1] = ffma2(pd, vv.y, accv2[2 * t + 1]);
                }
            }
        }
        __syncthreads();
    }

    const float inv = 1.f / l;
    const size_t base = ((size_t)(b * TT + qi)) * CC + h * HD;
#pragma unroll
    for (int t = 0; t < HD / 2; t++) {
        float f0, f1;
        unpack2(accv2[t], f0, f1);
        f0 *= inv; f1 *= inv;
        __nv_bfloat16 h0, l0, h1, l1;
        split_bf16(f0, h0, l0);
        split_bf16(f1, h1, l1);
        *(__nv_bfloat162*)(g_Yh + base + 2 * t) = __halves2bfloat162(h0, h1);
        *(__nv_bfloat162*)(g_Yl + base + 2 * t) = __halves2bfloat162(l0, l1);
    }
}

// ---------------------------------------------------------------------------
extern "C" void kernel_launch(void* const* d_in, const int* in_sizes, int n_in,
                              void* d_out, int out_size)
{
    const float* x  = (const float*)d_in[0];
    const float* Wq = (const float*)d_in[1];
    const float* bq = (const float*)d_in[2];
    const float* Wk = (const float*)d_in[3];
    const float* bk = (const float*)d_in[4];
    const float* Wv = (const float*)d_in[5];
    const float* bv = (const float*)d_in[6];
    const float* Wp = (const float*)d_in[7];
    const float* bp = (const float*)d_in[8];
    float* out = (float*)d_out;

    float *Q, *Kp, *Vp;
    __nv_bfloat16 *Xh, *Xl, *Yh, *Yl, *Wth, *Wtl;
    cudaGetSymbolAddress((void**)&Q,   g_Q);
    cudaGetSymbolAddress((void**)&Kp,  g_K);
    cudaGetSymbolAddress((void**)&Vp,  g_V);
    cudaGetSymbolAddress((void**)&Xh,  g_Xh);
    cudaGetSymbolAddress((void**)&Xl,  g_Xl);
    cudaGetSymbolAddress((void**)&Yh,  g_Yh);
    cudaGetSymbolAddress((void**)&Yl,  g_Yl);
    cudaGetSymbolAddress((void**)&Wth, g_Wth);
    cudaGetSymbolAddress((void**)&Wtl, g_Wtl);

    cudaFuncSetAttribute(gemm_mma_kernel,
                         cudaFuncAttributeMaxDynamicSharedMemorySize, GEMM_SMEM);

    const size_t WSZ = (size_t)CC * CC;

    // 1) split x into bf16 hi/lo
    convert_split_kernel<<<1024, 256>>>(x, Xh, Xl, MM * CC / 4);

    // 2) transpose+split the 4 weights
    dim3 tgrd(CC / 32, CC / 32), tblk(32, 8);
    transpose_split_kernel<<<tgrd, tblk>>>(Wq, Wth + 0 * WSZ, Wtl + 0 * WSZ);
    transpose_split_kernel<<<tgrd, tblk>>>(Wk, Wth + 1 * WSZ, Wtl + 1 * WSZ);
    transpose_split_kernel<<<tgrd, tblk>>>(Wv, Wth + 2 * WSZ, Wtl + 2 * WSZ);
    transpose_split_kernel<<<tgrd, tblk>>>(Wp, Wth + 3 * WSZ, Wtl + 3 * WSZ);

    // 3) Q/K/V projections on tensor cores (mma.sync)
    dim3 ggrd(CC / 128, MM / 128);   // (8, 32) = 256 CTAs
    gemm_mma_kernel<<<ggrd, 256, GEMM_SMEM>>>(Xh, Xl, Wth + 0*WSZ, Wtl + 0*WSZ, bq, Q);
    gemm_mma_kernel<<<ggrd, 256, GEMM_SMEM>>>(Xh, Xl, Wth + 1*WSZ, Wtl + 1*WSZ, bk, Kp);
    gemm_mma_kernel<<<ggrd, 256, GEMM_SMEM>>>(Xh, Xl, Wth + 2*WSZ, Wtl + 2*WSZ, bv, Vp);

    // 4) attention (writes g_Yh / g_Yl)
    dim3 agrd(TT / 128, HH, BB);
    attn_kernel<<<agrd, 128>>>(Q, Kp, Vp);

    // 5) output projection
    gemm_mma_kernel<<<ggrd, 256, GEMM_SMEM>>>(Yh, Yl, Wth + 3*WSZ, Wtl + 3*WSZ, bp, out);

    (void)in_sizes; (void)n_in; (void)out_size;
}

// round 9
// speedup vs baseline: 3.2566x; 2.0305x over previous
#include <cuda_runtime.h>
#include <cuda_bf16.h>
#include <cstdint>

// Problem constants
#define BB 2
#define TT 2048
#define CC 1024
#define HH 16
#define HD 64
#define MM (BB*TT)   // 4096 rows

// 0.125 (1/sqrt(64)) * log2(e), folded into Q projection
#define SCALE_Q 0.18033688f

// ---------------------------------------------------------------------------
// Scratch (__device__ globals: allocation-free rule)
// ---------------------------------------------------------------------------
__device__ __nv_bfloat16 g_Xh[(size_t)MM*CC];
__device__ __nv_bfloat16 g_Xl[(size_t)MM*CC];
__device__ __nv_bfloat16 g_Qh[(size_t)MM*CC];
__device__ __nv_bfloat16 g_Ql[(size_t)MM*CC];
__device__ __nv_bfloat16 g_Kh[(size_t)MM*CC];
__device__ __nv_bfloat16 g_Kl[(size_t)MM*CC];
__device__ __nv_bfloat16 g_Vth[(size_t)MM*CC];  // V transposed per head [b,h,d,t]
__device__ __nv_bfloat16 g_Vtl[(size_t)MM*CC];
__device__ __nv_bfloat16 g_Yh[(size_t)MM*CC];
__device__ __nv_bfloat16 g_Yl[(size_t)MM*CC];
__device__ __nv_bfloat16 g_Wth[(size_t)4*CC*CC];
__device__ __nv_bfloat16 g_Wtl[(size_t)4*CC*CC];

// ---------------------------------------------------------------------------
// PTX helpers
// ---------------------------------------------------------------------------
__device__ __forceinline__ uint32_t smem_u32(const void* p) {
    uint32_t a;
    asm("{ .reg .u64 t; cvta.to.shared.u64 t, %1; cvt.u32.u64 %0, t; }" : "=r"(a) : "l"(p));
    return a;
}
__device__ __forceinline__ void cp_async16(uint32_t saddr, const void* gaddr) {
    asm volatile("cp.async.ca.shared.global [%0], [%1], 16;" :: "r"(saddr), "l"(gaddr));
}
#define CP_COMMIT() asm volatile("cp.async.commit_group;" ::: "memory")

__device__ __forceinline__ void ldmat_x4(uint32_t* r, uint32_t addr) {
    asm volatile("ldmatrix.sync.aligned.m8n8.x4.shared.b16 {%0,%1,%2,%3}, [%4];"
        : "=r"(r[0]), "=r"(r[1]), "=r"(r[2]), "=r"(r[3]) : "r"(addr));
}
__device__ __forceinline__ void ldmat_x2(uint32_t* r, uint32_t addr) {
    asm volatile("ldmatrix.sync.aligned.m8n8.x2.shared.b16 {%0,%1}, [%2];"
        : "=r"(r[0]), "=r"(r[1]) : "r"(addr));
}
__device__ __forceinline__ void mma_bf16(float* c, const uint32_t* a, const uint32_t* b) {
    asm volatile("mma.sync.aligned.m16n8k16.row.col.f32.bf16.bf16.f32 "
        "{%0,%1,%2,%3}, {%4,%5,%6,%7}, {%8,%9}, {%0,%1,%2,%3};"
        : "+f"(c[0]), "+f"(c[1]), "+f"(c[2]), "+f"(c[3])
        : "r"(a[0]), "r"(a[1]), "r"(a[2]), "r"(a[3]), "r"(b[0]), "r"(b[1]));
}
__device__ __forceinline__ uint32_t pack_bf16x2(float lo, float hi) {
    uint32_t d;
    asm("cvt.rn.satfinite.bf16x2.f32 %0, %1, %2;" : "=r"(d) : "f"(hi), "f"(lo));
    return d;
}
__device__ __forceinline__ float ex2f(float x) {
    float y; asm("ex2.approx.f32 %0, %1;" : "=f"(y) : "f"(x)); return y;
}

// ---------------------------------------------------------------------------
// Split-precision conversion kernels (round-nearest split for GEMM inputs)
// ---------------------------------------------------------------------------
__device__ __forceinline__ void split_bf16(float v, __nv_bfloat16& h, __nv_bfloat16& l) {
    h = __float2bfloat16(v);
    l = __float2bfloat16(v - __bfloat162float(h));
}

__global__ void convert_split_kernel(const float* __restrict__ in,
                                     __nv_bfloat16* __restrict__ oh,
                                     __nv_bfloat16* __restrict__ ol, int n4)
{
    for (int i = blockIdx.x * blockDim.x + threadIdx.x; i < n4; i += gridDim.x * blockDim.x) {
        float4 v = ((const float4*)in)[i];
        __nv_bfloat16 h0,l0,h1,l1,h2,l2,h3,l3;
        split_bf16(v.x,h0,l0); split_bf16(v.y,h1,l1);
        split_bf16(v.z,h2,l2); split_bf16(v.w,h3,l3);
        ((__nv_bfloat162*)oh)[2*i]   = __halves2bfloat162(h0,h1);
        ((__nv_bfloat162*)oh)[2*i+1] = __halves2bfloat162(h2,h3);
        ((__nv_bfloat162*)ol)[2*i]   = __halves2bfloat162(l0,l1);
        ((__nv_bfloat162*)ol)[2*i+1] = __halves2bfloat162(l2,l3);
    }
}

// W[K,N] -> Wt[N,K] split into hi/lo bf16
__global__ void transpose_split_kernel(const float* __restrict__ W,
                                       __nv_bfloat16* __restrict__ Th,
                                       __nv_bfloat16* __restrict__ Tl)
{
    __shared__ float t[32][33];
    int xi = blockIdx.x * 32 + threadIdx.x;
    int yi = blockIdx.y * 32 + threadIdx.y;
#pragma unroll
    for (int j = 0; j < 32; j += 8)
        t[threadIdx.y + j][threadIdx.x] = W[(size_t)(yi + j) * CC + xi];
    __syncthreads();
    int xo = blockIdx.y * 32 + threadIdx.x;
    int yo = blockIdx.x * 32 + threadIdx.y;
#pragma unroll
    for (int j = 0; j < 32; j += 8) {
        float v = t[threadIdx.x][threadIdx.y + j];
        __nv_bfloat16 h, l;
        split_bf16(v, h, l);
        Th[(size_t)(yo + j) * CC + xo] = h;
        Tl[(size_t)(yo + j) * CC + xo] = l;
    }
}

// ---------------------------------------------------------------------------
// mma.sync split-bf16 GEMM: [4096,1024] = A @ Wt^T + bias, then epilogue mode:
//   mode 0: fp32 row-major to outf
//   mode 1: truncation-split bf16 hi/lo row-major to outh/outl  (Q, K)
//   mode 2: truncation-split bf16 hi/lo transposed-per-head     (V)
// scale applied to (acc + bias).
// ---------------------------------------------------------------------------
#define BK 32
#define PITCH 40
#define TILE_BYTES (128 * PITCH * 2)
#define AH_OFF 0
#define AL_OFF (2 * TILE_BYTES)
#define BH_OFF (4 * TILE_BYTES)
#define BL_OFF (6 * TILE_BYTES)
#define GEMM_SMEM (8 * TILE_BYTES)     // 81920 B

__global__ __launch_bounds__(256) void gemm_mma_kernel(
    const __nv_bfloat16* __restrict__ Ah, const __nv_bfloat16* __restrict__ Al,
    const __nv_bfloat16* __restrict__ Bh, const __nv_bfloat16* __restrict__ Bl,
    const float* __restrict__ bias,
    float* __restrict__ outf,
    __nv_bfloat16* __restrict__ outh, __nv_bfloat16* __restrict__ outl,
    int mode, float scale)
{
    extern __shared__ char smem[];
    const uint32_t sbase = smem_u32(smem);
    const int tid  = threadIdx.x;
    const int lane = tid & 31;
    const int wid  = tid >> 5;
    const int warp_m = wid >> 2;
    const int warp_n = wid & 3;

    const int rowBase = blockIdx.y * 128;
    const int colBase = blockIdx.x * 128;

    float acc[4][4][4];
#pragma unroll
    for (int i = 0; i < 4; i++)
#pragma unroll
        for (int j = 0; j < 4; j++)
#pragma unroll
            for (int r = 0; r < 4; r++) acc[i][j][r] = 0.f;

    auto load_stage = [&](int stg, int kc0) {
        const uint32_t so = (uint32_t)stg * TILE_BYTES;
#pragma unroll
        for (int it = 0; it < 2; it++) {
            int v = tid + it * 256;
            int r = v >> 2;
            int cv = v & 3;
            uint32_t doff = so + (uint32_t)(r * 80 + cv * 16);
            size_t gA = (size_t)(rowBase + r) * CC + kc0 + cv * 8;
            size_t gB = (size_t)(colBase + r) * CC + kc0 + cv * 8;
            cp_async16(sbase + AH_OFF + doff, Ah + gA);
            cp_async16(sbase + AL_OFF + doff, Al + gA);
            cp_async16(sbase + BH_OFF + doff, Bh + gB);
            cp_async16(sbase + BL_OFF + doff, Bl + gB);
        }
        CP_COMMIT();
    };

    const int arow  = (lane & 7) + ((lane >> 3) & 1) * 8;
    const int akoff = (lane >> 4) * 8;
    const int l2    = lane & 15;
    const int brow  = l2 & 7;
    const int bkoff = (l2 >> 3) * 8;

    auto compute_stage = [&](int stg) {
        const uint32_t so = (uint32_t)stg * TILE_BYTES;
#pragma unroll
        for (int ks = 0; ks < 2; ks++) {
            const int k0 = ks * 16;
            uint32_t ah[4][4], al[4][4], bh[4][2], bl[4][2];
#pragma unroll
            for (int mt = 0; mt < 4; mt++) {
                int row = warp_m * 64 + mt * 16 + arow;
                uint32_t off = so + (uint32_t)(row * 80 + (k0 + akoff) * 2);
                ldmat_x4(ah[mt], sbase + AH_OFF + off);
                ldmat_x4(al[mt], sbase + AL_OFF + off);
            }
#pragma unroll
            for (int nt = 0; nt < 4; nt++) {
                int row = warp_n * 32 + nt * 8 + brow;
                uint32_t off = so + (uint32_t)(row * 80 + (k0 + bkoff) * 2);
                ldmat_x2(bh[nt], sbase + BH_OFF + off);
                ldmat_x2(bl[nt], sbase + BL_OFF + off);
            }
#pragma unroll
            for (int mt = 0; mt < 4; mt++)
#pragma unroll
                for (int nt = 0; nt < 4; nt++) {
                    mma_bf16(acc[mt][nt], ah[mt], bh[nt]);
                    mma_bf16(acc[mt][nt], ah[mt], bl[nt]);
                    mma_bf16(acc[mt][nt], al[mt], bh[nt]);
                }
        }
    };

    const int NCHUNK = CC / BK;
    load_stage(0, 0);
    for (int c = 0; c < NCHUNK; c++) {
        if (c + 1 < NCHUNK) {
            load_stage((c + 1) & 1, (c + 1) * BK);
            asm volatile("cp.async.wait_group 1;" ::: "memory");
        } else {
            asm volatile("cp.async.wait_group 0;" ::: "memory");
        }
        __syncthreads();
        compute_stage(c & 1);
        __syncthreads();
    }

    const int gg  = lane >> 2;
    const int tg2 = (lane & 3) * 2;
#pragma unroll
    for (int mt = 0; mt < 4; mt++) {
        int row0 = rowBase + warp_m * 64 + mt * 16 + gg;
#pragma unroll
        for (int nt = 0; nt < 4; nt++) {
            int col = colBase + warp_n * 32 + nt * 8 + tg2;
            float2 bv = *(const float2*)(bias + col);
            float o00 = (acc[mt][nt][0] + bv.x) * scale;
            float o01 = (acc[mt][nt][1] + bv.y) * scale;
            float o10 = (acc[mt][nt][2] + bv.x) * scale;
            float o11 = (acc[mt][nt][3] + bv.y) * scale;
            if (mode == 0) {
                *(float2*)(outf + (size_t)row0 * CC + col) = make_float2(o00, o01);
                *(float2*)(outf + (size_t)(row0 + 8) * CC + col) = make_float2(o10, o11);
            } else if (mode == 1) {
                uint32_t u0 = __float_as_uint(o00), u1 = __float_as_uint(o01);
                uint32_t u2 = __float_as_uint(o10), u3 = __float_as_uint(o11);
                uint16_t* oh16 = (uint16_t*)outh;
                uint16_t* ol16 = (uint16_t*)outl;
                *(uint32_t*)(oh16 + (size_t)row0 * CC + col) = __byte_perm(u0, u1, 0x7632);
                *(uint32_t*)(oh16 + (size_t)(row0 + 8) * CC + col) = __byte_perm(u2, u3, 0x7632);
                *(uint32_t*)(ol16 + (size_t)row0 * CC + col) =
                    pack_bf16x2(o00 - __uint_as_float(u0 & 0xFFFF0000u),
                                o01 - __uint_as_float(u1 & 0xFFFF0000u));
                *(uint32_t*)(ol16 + (size_t)(row0 + 8) * CC + col) =
                    pack_bf16x2(o10 - __uint_as_float(u2 & 0xFFFF0000u),
                                o11 - __uint_as_float(u3 & 0xFFFF0000u));
            } else {
                // V transposed per head: Vt[((b*H + h)*HD + d)*T + t]
                int hh = col >> 6, d = col & 63;
                int b0 = row0 >> 11, t0 = row0 & 2047;
                size_t base = (((size_t)b0 * HH + hh) * HD + d) * TT + t0;
                uint16_t* oh16 = (uint16_t*)outh;
                __nv_bfloat16* ol16 = outl;
                uint32_t u;
                u = __float_as_uint(o00);
                oh16[base] = (uint16_t)(u >> 16);
                ol16[base] = __float2bfloat16(o00 - __uint_as_float(u & 0xFFFF0000u));
                u = __float_as_uint(o01);
                oh16[base + TT] = (uint16_t)(u >> 16);
                ol16[base + TT] = __float2bfloat16(o01 - __uint_as_float(u & 0xFFFF0000u));
                u = __float_as_uint(o10);
                oh16[base + 8] = (uint16_t)(u >> 16);
                ol16[base + 8] = __float2bfloat16(o10 - __uint_as_float(u & 0xFFFF0000u));
                u = __float_as_uint(o11);
                oh16[base + TT + 8] = (uint16_t)(u >> 16);
                ol16[base + TT + 8] = __float2bfloat16(o11 - __uint_as_float(u & 0xFFFF0000u));
            }
        }
    }
}

// ---------------------------------------------------------------------------
// Tensor-core causal flash attention.
// CTA: 128 q-rows, 4 warps (32 rows each). KV blocks of 64.
// S = QhKh + QhKl + QlKh;  P trunc-split;  O = PhVh + PlVh + PhVl.
// Q has 0.125*log2e folded in; softmax via ex2.
// Writes Y as trunc-split bf16 hi/lo (g_Yh/g_Yl).
// ---------------------------------------------------------------------------
#define APITCH 144            // 72 bf16 per row (bytes)
#define SQH 0
#define SQL 18432
#define SKH 36864
#define SKL 46080
#define SVH 55296
#define SVL 64512
#define ATTN_SMEM 73728

__global__ __launch_bounds__(128) void attn_mma_kernel(
    const __nv_bfloat16* __restrict__ Qh_, const __nv_bfloat16* __restrict__ Ql_,
    const __nv_bfloat16* __restrict__ Kh_, const __nv_bfloat16* __restrict__ Kl_,
    const __nv_bfloat16* __restrict__ Vh_, const __nv_bfloat16* __restrict__ Vl_)
{
    extern __shared__ char smem[];
    const uint32_t sb = smem_u32(smem);
    const int tid = threadIdx.x, lane = tid & 31, wid = tid >> 5;
    const int qb = gridDim.x - 1 - blockIdx.x;   // heavy blocks first
    const int h  = blockIdx.y, b = blockIdx.z;

    // Q tile: 128 rows x 64 bf16, hi/lo
#pragma unroll
    for (int i = 0; i < 8; i++) {
        int v = tid + i * 128, r = v >> 3, c = v & 7;
        uint32_t so = (uint32_t)(r * APITCH + c * 16);
        size_t g = ((size_t)b * TT + qb * 128 + r) * CC + h * HD + c * 8;
        cp_async16(sb + SQH + so, Qh_ + g);
        cp_async16(sb + SQL + so, Ql_ + g);
    }
    CP_COMMIT();

    const int g4 = lane >> 2, t4 = lane & 3;
    const int arow  = (lane & 7) + ((lane >> 3) & 1) * 8;
    const int akoff = (lane >> 4) * 8;
    const int l2 = lane & 15, brow = l2 & 7, bkoff = (l2 >> 3) * 8;

    float O[2][8][4];
#pragma unroll
    for (int mt = 0; mt < 2; mt++)
#pragma unroll
        for (int nt = 0; nt < 8; nt++)
#pragma unroll
            for (int r = 0; r < 4; r++) O[mt][nt][r] = 0.f;
    float mr[2][2] = {{-1e30f, -1e30f}, {-1e30f, -1e30f}};
    float lr[2][2] = {{0.f, 0.f}, {0.f, 0.f}};

    const int nkv = qb * 2 + 2;
    for (int kb = 0; kb < nkv; kb++) {
        // K tile [64 keys][64 hd], Vt tile [64 hd][64 keys], hi/lo
#pragma unroll
        for (int i = 0; i < 4; i++) {
            int v = tid + i * 128, r = v >> 3, c = v & 7;
            uint32_t so = (uint32_t)(r * APITCH + c * 16);
            size_t gk = ((size_t)b * TT + kb * 64 + r) * CC + h * HD + c * 8;
            cp_async16(sb + SKH + so, Kh_ + gk);
            cp_async16(sb + SKL + so, Kl_ + gk);
            size_t gv = (((size_t)b * HH + h) * HD + r) * TT + kb * 64 + c * 8;
            cp_async16(sb + SVH + so, Vh_ + gv);
            cp_async16(sb + SVL + so, Vl_ + gv);
        }
        CP_COMMIT();
        asm volatile("cp.async.wait_group 0;" ::: "memory");
        __syncthreads();

        // ---- S = Q K^T ----
        float S[2][8][4];
#pragma unroll
        for (int mt = 0; mt < 2; mt++)
#pragma unroll
            for (int nt = 0; nt < 8; nt++)
#pragma unroll
                for (int r = 0; r < 4; r++) S[mt][nt][r] = 0.f;
#pragma unroll
        for (int kc = 0; kc < 4; kc++) {
            uint32_t ah[2][4], al[2][4], bh2[8][2], bl2[8][2];
#pragma unroll
            for (int mt = 0; mt < 2; mt++) {
                int row = wid * 32 + mt * 16 + arow;
                uint32_t off = (uint32_t)(row * APITCH + (kc * 16 + akoff) * 2);
                ldmat_x4(ah[mt], sb + SQH + off);
                ldmat_x4(al[mt], sb + SQL + off);
            }
#pragma unroll
            for (int nt = 0; nt < 8; nt++) {
                int row = nt * 8 + brow;
                uint32_t off = (uint32_t)(row * APITCH + (kc * 16 + bkoff) * 2);
                ldmat_x2(bh2[nt], sb + SKH + off);
                ldmat_x2(bl2[nt], sb + SKL + off);
            }
#pragma unroll
            for (int mt = 0; mt < 2; mt++)
#pragma unroll
                for (int nt = 0; nt < 8; nt++) {
                    mma_bf16(S[mt][nt], ah[mt], bh2[nt]);
                    mma_bf16(S[mt][nt], ah[mt], bl2[nt]);
                    mma_bf16(S[mt][nt], al[mt], bh2[nt]);
                }
        }

        // ---- causal mask ----
#pragma unroll
        for (int mt = 0; mt < 2; mt++) {
            int r0 = qb * 128 + wid * 32 + mt * 16 + g4;
#pragma unroll
            for (int nt = 0; nt < 8; nt++) {
                int k0 = kb * 64 + nt * 8 + 2 * t4;
                if (k0     > r0)     S[mt][nt][0] = -1e30f;
                if (k0 + 1 > r0)     S[mt][nt][1] = -1e30f;
                if (k0     > r0 + 8) S[mt][nt][2] = -1e30f;
                if (k0 + 1 > r0 + 8) S[mt][nt][3] = -1e30f;
            }
        }

        // ---- online softmax ----
#pragma unroll
        for (int mt = 0; mt < 2; mt++) {
#pragma unroll
            for (int rh = 0; rh < 2; rh++) {
                float mx = -1e30f;
#pragma unroll
                for (int nt = 0; nt < 8; nt++)
                    mx = fmaxf(mx, fmaxf(S[mt][nt][rh * 2], S[mt][nt][rh * 2 + 1]));
                mx = fmaxf(mx, __shfl_xor_sync(0xffffffffu, mx, 1));
                mx = fmaxf(mx, __shfl_xor_sync(0xffffffffu, mx, 2));
                float mnew = fmaxf(mr[mt][rh], mx);
                float corr = ex2f(mr[mt][rh] - mnew);
                mr[mt][rh] = mnew;
                float sum = 0.f;
#pragma unroll
                for (int nt = 0; nt < 8; nt++) {
                    float p0 = ex2f(S[mt][nt][rh * 2]     - mnew);
                    float p1 = ex2f(S[mt][nt][rh * 2 + 1] - mnew);
                    S[mt][nt][rh * 2] = p0; S[mt][nt][rh * 2 + 1] = p1;
                    sum += p0 + p1;
                }
                sum += __shfl_xor_sync(0xffffffffu, sum, 1);
                sum += __shfl_xor_sync(0xffffffffu, sum, 2);
                lr[mt][rh] = lr[mt][rh] * corr + sum;
#pragma unroll
                for (int nt = 0; nt < 8; nt++) {
                    O[mt][nt][rh * 2]     *= corr;
                    O[mt][nt][rh * 2 + 1] *= corr;
                }
            }
        }

        // ---- O += P V ----
#pragma unroll
        for (int kc = 0; kc < 4; kc++) {
            uint32_t ph[2][4], pl[2][4];
#pragma unroll
            for (int mt = 0; mt < 2; mt++)
#pragma unroll
                for (int half = 0; half < 2; half++) {
                    int nt = 2 * kc + half;
                    uint32_t u0 = __float_as_uint(S[mt][nt][0]);
                    uint32_t u1 = __float_as_uint(S[mt][nt][1]);
                    uint32_t u2 = __float_as_uint(S[mt][nt][2]);
                    uint32_t u3 = __float_as_uint(S[mt][nt][3]);
                    ph[mt][half * 2 + 0] = __byte_perm(u0, u1, 0x7632);
                    ph[mt][half * 2 + 1] = __byte_perm(u2, u3, 0x7632);
                    float q0 = S[mt][nt][0] - __uint_as_float(u0 & 0xFFFF0000u);
                    float q1 = S[mt][nt][1] - __uint_as_float(u1 & 0xFFFF0000u);
                    float q2 = S[mt][nt][2] - __uint_as_float(u2 & 0xFFFF0000u);
                    float q3 = S[mt][nt][3] - __uint_as_float(u3 & 0xFFFF0000u);
                    pl[mt][half * 2 + 0] = pack_bf16x2(q0, q1);
                    pl[mt][half * 2 + 1] = pack_bf16x2(q2, q3);
                }
            uint32_t vh2[2], vl2[2];
#pragma unroll
            for (int nt = 0; nt < 8; nt++) {
                int row = nt * 8 + brow;
                uint32_t off = (uint32_t)(row * APITCH + (kc * 16 + bkoff) * 2);
                ldmat_x2(vh2, sb + SVH + off);
                ldmat_x2(vl2, sb + SVL + off);
#pragma unroll
                for (int mt = 0; mt < 2; mt++) {
                    mma_bf16(O[mt][nt], ph[mt], vh2);
                    mma_bf16(O[mt][nt], pl[mt], vh2);
                    mma_bf16(O[mt][nt], ph[mt], vl2);
                }
            }
        }
        __syncthreads();   // all warps done with K/V smem before next load
    }

    // ---- normalize + write trunc-split Y ----
#pragma unroll
    for (int mt = 0; mt < 2; mt++) {
        float i0 = 1.f / lr[mt][0];
        float i1 = 1.f / lr[mt][1];
        int r0 = qb * 128 + wid * 32 + mt * 16 + g4;
#pragma unroll
        for (int nt = 0; nt < 8; nt++) {
            int col = h * HD + nt * 8 + 2 * t4;
            float f0 = O[mt][nt][0] * i0, f1 = O[mt][nt][1] * i0;
            uint32_t u0 = __float_as_uint(f0), u1 = __float_as_uint(f1);
            size_t off0 = ((size_t)b * TT + r0) * CC + col;
            *(uint32_t*)((uint16_t*)g_Yh + off0) = __byte_perm(u0, u1, 0x7632);
            *(uint32_t*)((uint16_t*)g_Yl + off0) =
                pack_bf16x2(f0 - __uint_as_float(u0 & 0xFFFF0000u),
                            f1 - __uint_as_float(u1 & 0xFFFF0000u));
            float f2 = O[mt][nt][2] * i1, f3 = O[mt][nt][3] * i1;
            uint32_t u2 = __float_as_uint(f2), u3 = __float_as_uint(f3);
            size_t off1 = ((size_t)b * TT + r0 + 8) * CC + col;
            *(uint32_t*)((uint16_t*)g_Yh + off1) = __byte_perm(u2, u3, 0x7632);
            *(uint32_t*)((uint16_t*)g_Yl + off1) =
                pack_bf16x2(f2 - __uint_as_float(u2 & 0xFFFF0000u),
                            f3 - __uint_as_float(u3 & 0xFFFF0000u));
        }
    }
}

// ---------------------------------------------------------------------------
extern "C" void kernel_launch(void* const* d_in, const int* in_sizes, int n_in,
                              void* d_out, int out_size)
{
    const float* x  = (const float*)d_in[0];
    const float* Wq = (const float*)d_in[1];
    const float* bq = (const float*)d_in[2];
    const float* Wk = (const float*)d_in[3];
    const float* bk = (const float*)d_in[4];
    const float* Wv = (const float*)d_in[5];
    const float* bv = (const float*)d_in[6];
    const float* Wp = (const float*)d_in[7];
    const float* bp = (const float*)d_in[8];
    float* out = (float*)d_out;

    __nv_bfloat16 *Xh, *Xl, *Qh, *Ql, *Kh, *Kl, *Vth, *Vtl, *Yh, *Yl, *Wth, *Wtl;
    cudaGetSymbolAddress((void**)&Xh,  g_Xh);
    cudaGetSymbolAddress((void**)&Xl,  g_Xl);
    cudaGetSymbolAddress((void**)&Qh,  g_Qh);
    cudaGetSymbolAddress((void**)&Ql,  g_Ql);
    cudaGetSymbolAddress((void**)&Kh,  g_Kh);
    cudaGetSymbolAddress((void**)&Kl,  g_Kl);
    cudaGetSymbolAddress((void**)&Vth, g_Vth);
    cudaGetSymbolAddress((void**)&Vtl, g_Vtl);
    cudaGetSymbolAddress((void**)&Yh,  g_Yh);
    cudaGetSymbolAddress((void**)&Yl,  g_Yl);
    cudaGetSymbolAddress((void**)&Wth, g_Wth);
    cudaGetSymbolAddress((void**)&Wtl, g_Wtl);

    cudaFuncSetAttribute(gemm_mma_kernel,
                         cudaFuncAttributeMaxDynamicSharedMemorySize, GEMM_SMEM);
    cudaFuncSetAttribute(attn_mma_kernel,
                         cudaFuncAttributeMaxDynamicSharedMemorySize, ATTN_SMEM);

    const size_t WSZ = (size_t)CC * CC;

    // 1) split x into bf16 hi/lo
    convert_split_kernel<<<1024, 256>>>(x, Xh, Xl, MM * CC / 4);

    // 2) transpose+split the 4 weights
    dim3 tgrd(CC / 32, CC / 32), tblk(32, 8);
    transpose_split_kernel<<<tgrd, tblk>>>(Wq, Wth + 0 * WSZ, Wtl + 0 * WSZ);
    transpose_split_kernel<<<tgrd, tblk>>>(Wk, Wth + 1 * WSZ, Wtl + 1 * WSZ);
    transpose_split_kernel<<<tgrd, tblk>>>(Wv, Wth + 2 * WSZ, Wtl + 2 * WSZ);
    transpose_split_kernel<<<tgrd, tblk>>>(Wp, Wth + 3 * WSZ, Wtl + 3 * WSZ);

    // 3) projections: Q (scaled, split), K (split), V (split + transposed)
    dim3 ggrd(CC / 128, MM / 128);
    gemm_mma_kernel<<<ggrd, 256, GEMM_SMEM>>>(Xh, Xl, Wth + 0*WSZ, Wtl + 0*WSZ, bq,
                                              nullptr, Qh, Ql, 1, SCALE_Q);
    gemm_mma_kernel<<<ggrd, 256, GEMM_SMEM>>>(Xh, Xl, Wth + 1*WSZ, Wtl + 1*WSZ, bk,
                                              nullptr, Kh, Kl, 1, 1.0f);
    gemm_mma_kernel<<<ggrd, 256, GEMM_SMEM>>>(Xh, Xl, Wth + 2*WSZ, Wtl + 2*WSZ, bv,
                                              nullptr, Vth, Vtl, 2, 1.0f);

    // 4) tensor-core flash attention
    dim3 agrd(TT / 128, HH, BB);
    attn_mma_kernel<<<agrd, 128, ATTN_SMEM>>>(Qh, Ql, Kh, Kl, Vth, Vtl);

    // 5) output projection (fp32 out)
    gemm_mma_kernel<<<ggrd, 256, GEMM_SMEM>>>(Yh, Yl, Wth + 3*WSZ, Wtl + 3*WSZ, bp,
                                              out, nullptr, nullptr, 0, 1.0f);

    (void)in_sizes; (void)n_in; (void)out_size;
}